// round 7
// baseline (speedup 1.0000x reference)
#include <cuda_runtime.h>
#include <stdint.h>

#define D 128
#define MAX_N (1 << 18)
#define MAX_E (1 << 21)
#define GB 8                     // gather batch depth

__device__ int g_cnt_tot[MAX_N];
__device__ int g_cnt_g[MAX_N];
__device__ int g_off[MAX_N + 2];
__device__ int g_cur[MAX_N];
__device__ int g_perm[MAX_E];

// ---------------------------------------------------------------------------
// K0: zero output + both count arrays
// ---------------------------------------------------------------------------
__global__ void zero_kernel(float4* __restrict__ out4, long long n4, int n4c) {
    long long i = (long long)blockIdx.x * blockDim.x + threadIdx.x;
    long long stride = (long long)gridDim.x * blockDim.x;
    for (long long k = i; k < n4; k += stride)
        out4[k] = make_float4(0.f, 0.f, 0.f, 0.f);
    for (long long k = i; k < n4c; k += stride) {
        g_cnt_tot[k] = 0;
        g_cnt_g[k] = 0;
    }
}

// ---------------------------------------------------------------------------
// K1: histogram (total counts; G-subset counts for edges >= Ea). 4 edges/thread.
// ---------------------------------------------------------------------------
__global__ void hist_kernel(const int* __restrict__ index, long long E, long long Ea) {
    long long base = ((long long)blockIdx.x * blockDim.x + threadIdx.x) * 4;
    if (base >= E) return;
    if (base + 4 <= E) {
        int4 v = *(const int4*)(index + base);   // Ea & base are 4-aligned
        atomicAdd(&g_cnt_tot[v.x], 1);
        atomicAdd(&g_cnt_tot[v.y], 1);
        atomicAdd(&g_cnt_tot[v.z], 1);
        atomicAdd(&g_cnt_tot[v.w], 1);
        if (base >= Ea) {
            atomicAdd(&g_cnt_g[v.x], 1);
            atomicAdd(&g_cnt_g[v.y], 1);
            atomicAdd(&g_cnt_g[v.z], 1);
            atomicAdd(&g_cnt_g[v.w], 1);
        }
    } else {
        for (long long e = base; e < E; e++) {
            int s = __ldg(&index[e]);
            atomicAdd(&g_cnt_tot[s], 1);
            if (e >= Ea) atomicAdd(&g_cnt_g[s], 1);
        }
    }
}

// ---------------------------------------------------------------------------
// K2: exclusive scan of g_cnt_g -> g_off / g_cur. Single 1024-thread block.
// ---------------------------------------------------------------------------
__global__ __launch_bounds__(1024) void scan_kernel(int N) {
    __shared__ int s[1024];
    int t = threadIdx.x;
    int n4 = (N + 3) >> 2;
    int chunk = (n4 + 1023) >> 10;
    int b4 = t * chunk;
    int e4 = min(b4 + chunk, n4);
    const int4* c4 = (const int4*)g_cnt_g;

    int sum = 0;
    for (int i = b4; i < e4; i++) {
        int4 v = c4[i];
        sum += v.x + v.y + v.z + v.w;
    }
    s[t] = sum;
    __syncthreads();
    for (int d = 1; d < 1024; d <<= 1) {
        int v = (t >= d) ? s[t - d] : 0;
        __syncthreads();
        s[t] += v;
        __syncthreads();
    }
    int run = (t == 0) ? 0 : s[t - 1];
    for (int i = b4; i < e4; i++) {
        int4 v = c4[i];
        int p = i * 4;
        g_off[p] = run; g_cur[p] = run; run += v.x;
        g_off[p + 1] = run; g_cur[p + 1] = run; run += v.y;
        g_off[p + 2] = run; g_cur[p + 2] = run; run += v.z;
        g_off[p + 3] = run; g_cur[p + 3] = run; run += v.w;
    }
    if (t == 1023) g_off[N] = s[1023];
}

// ---------------------------------------------------------------------------
// K3: scatter G-edge ids into segment-grouped permutation. 4 edges/thread.
// ---------------------------------------------------------------------------
__global__ void scatter_kernel(const int* __restrict__ index, long long Ea, long long E) {
    long long base = Ea + ((long long)blockIdx.x * blockDim.x + threadIdx.x) * 4;
    if (base >= E) return;
    if (base + 4 <= E) {
        int4 v = *(const int4*)(index + base);
        int p0 = atomicAdd(&g_cur[v.x], 1);
        int p1 = atomicAdd(&g_cur[v.y], 1);
        int p2 = atomicAdd(&g_cur[v.z], 1);
        int p3 = atomicAdd(&g_cur[v.w], 1);
        g_perm[p0] = (int)base;
        g_perm[p1] = (int)(base + 1);
        g_perm[p2] = (int)(base + 2);
        g_perm[p3] = (int)(base + 3);
    } else {
        for (long long e = base; e < E; e++) {
            int p = atomicAdd(&g_cur[__ldg(&index[e])], 1);
            g_perm[p] = (int)e;
        }
    }
}

// ---------------------------------------------------------------------------
// K4: fused scatter. Blocks 3:1 = REDG (edges [0,Ea)) : gather (sorted G-edges).
//     REDG path saturates L2 RMW; gather path saturates DRAM random reads.
// ---------------------------------------------------------------------------
__global__ __launch_bounds__(256) void hybrid_kernel(
        const float4* __restrict__ msg4,
        const int* __restrict__ index,
        float* __restrict__ out,
        long long Ea, int N, long long Ba) {
    int grp = blockIdx.x >> 2;
    int r = blockIdx.x & 3;
    int warp = threadIdx.x >> 5;
    int lane = threadIdx.x & 31;

    if (r < 3) {
        // -------- REDG path: 8 warps x 4 edges per block --------
        long long blk = (long long)grp * 3 + r;
        if (blk >= Ba) return;
        long long base = blk * 32 + (long long)warp * 4;
        if (base >= Ea) return;
        int nb = (int)min(4LL, Ea - base);

        int seg_l = (lane < nb) ? __ldg(&index[base + lane]) : 0;
        float4 v[4];
#pragma unroll
        for (int e = 0; e < 4; e++)
            if (e < nb) v[e] = __ldg(&msg4[(base + e) * (D / 4) + lane]);
#pragma unroll
        for (int e = 0; e < 4; e++) {
            if (e >= nb) break;
            int seg = __shfl_sync(0xffffffffu, seg_l, e);
            float* dst = out + (long long)seg * D + lane * 4;
            asm volatile("red.global.add.v4.f32 [%0], {%1,%2,%3,%4};"
                         :: "l"(dst), "f"(v[e].x), "f"(v[e].y),
                            "f"(v[e].z), "f"(v[e].w) : "memory");
        }
    } else {
        // -------- gather path: one warp per segment --------
        int seg = grp * 8 + warp;
        if (seg >= N) return;
        int beg = g_off[seg];
        int end = g_off[seg + 1];
        if (beg == end) return;

        float4 acc = make_float4(0.f, 0.f, 0.f, 0.f);
        int i = beg;
        while (i < end) {
            int nb = min(end - i, GB);
            int e = (lane < nb) ? g_perm[i + lane] : 0;
#pragma unroll
            for (int j = 0; j < GB; j++) {
                if (j >= nb) break;
                int ej = __shfl_sync(0xffffffffu, e, j);
                float4 v = __ldg(&msg4[(long long)ej * (D / 4) + lane]);
                acc.x += v.x; acc.y += v.y; acc.z += v.z; acc.w += v.w;
            }
            i += nb;
        }
        float* dst = out + (long long)seg * D + lane * 4;
        asm volatile("red.global.add.v4.f32 [%0], {%1,%2,%3,%4};"
                     :: "l"(dst), "f"(acc.x), "f"(acc.y), "f"(acc.z), "f"(acc.w)
                     : "memory");
    }
}

// ---------------------------------------------------------------------------
// K5: divide sums by max(total count, 1)
// ---------------------------------------------------------------------------
__global__ void divide_kernel(float4* __restrict__ out4, int N) {
    long long i = (long long)blockIdx.x * blockDim.x + threadIdx.x;
    long long total = (long long)N * (D / 4);
    if (i >= total) return;
    int row = (int)(i >> 5);
    float c = (float)g_cnt_tot[row];
    float inv = 1.0f / fmaxf(c, 1.0f);
    float4 v = out4[i];
    v.x *= inv; v.y *= inv; v.z *= inv; v.w *= inv;
    out4[i] = v;
}

// ---------------------------------------------------------------------------
extern "C" void kernel_launch(void* const* d_in, const int* in_sizes, int n_in,
                              void* d_out, int out_size) {
    const float4* msg4  = (const float4*)d_in[0];
    const int*    index = (const int*)d_in[1];
    // d_in[2] (t) unused by the reference
    float* out = (float*)d_out;

    long long E = in_sizes[1];
    int N = out_size / D;
    long long n4 = (long long)out_size / 4;
    int n4c = (int)((N + 3) & ~3);

    long long Ea = (E * 5 / 8) & ~7LL;        // 62.5% via REDG, 4-aligned

    zero_kernel<<<2048, 256>>>((float4*)out, n4, n4c);
    hist_kernel<<<(int)((E + 1023) / 1024), 256>>>(index, E, Ea);
    scan_kernel<<<1, 1024>>>(N);
    {
        long long Eg = E - Ea;
        int blocks = (int)((Eg + 1023) / 1024);
        scatter_kernel<<<blocks, 256>>>(index, Ea, E);
    }
    {
        long long Ba = (Ea + 31) / 32;                 // REDG blocks
        long long Bg = ((long long)N + 7) / 8;         // gather blocks
        long long groups = (Ba + 2) / 3;
        if (Bg > groups) groups = Bg;
        int grid = (int)(groups * 4);
        hybrid_kernel<<<grid, 256>>>(msg4, index, out, Ea, N, Ba);
    }
    {
        long long total = (long long)N * (D / 4);
        int blocks = (int)((total + 255) / 256);
        divide_kernel<<<blocks, 256>>>((float4*)out, N);
    }
}

// round 8
// speedup vs baseline: 1.4557x; 1.4557x over previous
#include <cuda_runtime.h>
#include <stdint.h>

#define D 128
#define MAX_N (1 << 18)
#define RPB 128        // REDG edges per block (warps 0-3, 32 each)
#define TPB 128        // TMA edges per block  (warps 4-7, 32 each)
#define TEB 4          // TMA rows per staging buffer

__device__ int g_cnt[MAX_N];

// ---------------------------------------------------------------------------
// K0: zero output + counts
// ---------------------------------------------------------------------------
__global__ void zero_kernel(float4* __restrict__ out4, long long n4, int N) {
    long long i = (long long)blockIdx.x * blockDim.x + threadIdx.x;
    long long stride = (long long)gridDim.x * blockDim.x;
    for (long long k = i; k < n4; k += stride)
        out4[k] = make_float4(0.f, 0.f, 0.f, 0.f);
    for (long long k = i; k < N; k += stride)
        g_cnt[k] = 0;
}

// ---------------------------------------------------------------------------
// K1: fused scatter-add. EVERY block runs both paths concurrently:
//     warps 0-3 -> red.global.v4 (LSU pipe), edges [0, Ea)
//     warps 4-7 -> cp.reduce.async.bulk (TMA engine), edges [Ea, E)
//     so each SM's LSU and TMA engine overlap.
// ---------------------------------------------------------------------------
__global__ __launch_bounds__(256) void hybrid_kernel(
        const float4* __restrict__ msg4,
        const int* __restrict__ index,
        float* __restrict__ out,
        long long Ea, long long E) {
    __shared__ float4 sbuf[4][2][TEB][D / 4];   // 16 KB staging for TMA warps

    int warp = threadIdx.x >> 5;
    int lane = threadIdx.x & 31;

    if (warp < 4) {
        // ---------------- REDG path ----------------
        long long base = (long long)blockIdx.x * RPB + (long long)warp * 32;
#pragma unroll
        for (int b = 0; b < 8; b++) {
            long long e0 = base + b * 4;
            if (e0 >= Ea) break;
            int nb = (int)min(4LL, Ea - e0);

            int seg_l = (lane < nb) ? __ldg(&index[e0 + lane]) : 0;
            float4 v[4];
#pragma unroll
            for (int e = 0; e < 4; e++)
                if (e < nb) v[e] = __ldg(&msg4[(e0 + e) * (D / 4) + lane]);

#pragma unroll
            for (int e = 0; e < 4; e++) {
                if (e >= nb) break;
                int seg = __shfl_sync(0xffffffffu, seg_l, e);
                float* dst = out + (long long)seg * D + lane * 4;
                asm volatile("red.global.add.v4.f32 [%0], {%1,%2,%3,%4};"
                             :: "l"(dst), "f"(v[e].x), "f"(v[e].y),
                                "f"(v[e].z), "f"(v[e].w) : "memory");
                if (lane == e)
                    atomicAdd(&g_cnt[seg], 1);
            }
        }
    } else {
        // ---------------- TMA bulk-reduce path ----------------
        int tw = warp - 4;
        long long base = Ea + (long long)blockIdx.x * TPB + (long long)tw * 32;
        if (base >= E) return;

        int cur = 0;
#pragma unroll
        for (int b = 0; b < 8; b++) {
            long long e0 = base + b * TEB;
            if (e0 >= E) break;
            int nb = (int)min((long long)TEB, E - e0);

            int seg = (lane < nb) ? __ldg(&index[e0 + lane]) : 0;

#pragma unroll
            for (int e = 0; e < TEB; e++) {
                if (e >= nb) break;
                float4 v = __ldg(&msg4[(e0 + e) * (D / 4) + lane]);
                sbuf[tw][cur][e][lane] = v;
            }
            __syncwarp();

            if (lane < nb) {
                asm volatile("fence.proxy.async.shared::cta;" ::: "memory");
                uint32_t src = (uint32_t)__cvta_generic_to_shared(
                                   &sbuf[tw][cur][lane][0]);
                float* dst = out + (long long)seg * D;
                asm volatile(
                    "cp.reduce.async.bulk.global.shared::cta.bulk_group.add.f32 "
                    "[%0], [%1], %2;"
                    :: "l"(dst), "r"(src), "n"(D * 4) : "memory");
                asm volatile("cp.async.bulk.commit_group;" ::: "memory");
                atomicAdd(&g_cnt[seg], 1);
            }

            cur ^= 1;
            if (lane < TEB)
                asm volatile("cp.async.bulk.wait_group 1;" ::: "memory");
            __syncwarp();
        }
        if (lane < TEB)
            asm volatile("cp.async.bulk.wait_group 0;" ::: "memory");
    }
}

// ---------------------------------------------------------------------------
// K2: divide sums by max(count, 1)
// ---------------------------------------------------------------------------
__global__ void divide_kernel(float4* __restrict__ out4, int N) {
    long long i = (long long)blockIdx.x * blockDim.x + threadIdx.x;
    long long total = (long long)N * (D / 4);
    if (i >= total) return;
    int row = (int)(i >> 5);
    float c = (float)g_cnt[row];
    float inv = 1.0f / fmaxf(c, 1.0f);
    float4 v = out4[i];
    v.x *= inv; v.y *= inv; v.z *= inv; v.w *= inv;
    out4[i] = v;
}

// ---------------------------------------------------------------------------
extern "C" void kernel_launch(void* const* d_in, const int* in_sizes, int n_in,
                              void* d_out, int out_size) {
    const float4* msg4  = (const float4*)d_in[0];
    const int*    index = (const int*)d_in[1];
    // d_in[2] (t) unused by the reference
    float* out = (float*)d_out;

    long long E = in_sizes[1];
    int N = out_size / D;
    long long n4 = (long long)out_size / 4;

    // 50/50 split: LSU cost per REDG edge (~45 cyc) ~= TMA engine cost (~46)
    long long Ea = E / 2;
    long long Eg = E - Ea;

    zero_kernel<<<2048, 256>>>((float4*)out, n4, N);
    {
        long long ba = (Ea + RPB - 1) / RPB;
        long long bg = (Eg + TPB - 1) / TPB;
        int grid = (int)(ba > bg ? ba : bg);
        hybrid_kernel<<<grid, 256>>>(msg4, index, out, Ea, E);
    }
    {
        long long total = (long long)N * (D / 4);
        int blocks = (int)((total + 255) / 256);
        divide_kernel<<<blocks, 256>>>((float4*)out, N);
    }
}

// round 9
// speedup vs baseline: 1.5546x; 1.0680x over previous
#include <cuda_runtime.h>
#include <stdint.h>

#define D 128
#define MAX_N (1 << 18)

__device__ int   g_cnt[MAX_N];
__device__ float g_inv[MAX_N];

// ---------------------------------------------------------------------------
// K0: zero counts
// ---------------------------------------------------------------------------
__global__ void zero_cnt_kernel(int N) {
    int i = blockIdx.x * blockDim.x + threadIdx.x;
    if (i < N) g_cnt[i] = 0;
}

// ---------------------------------------------------------------------------
// K1: histogram of segment ids, 4 edges/thread (vectorized)
// ---------------------------------------------------------------------------
__global__ void hist_kernel(const int* __restrict__ index, long long E) {
    long long base = ((long long)blockIdx.x * blockDim.x + threadIdx.x) * 4;
    if (base >= E) return;
    if (base + 4 <= E) {
        int4 v = *(const int4*)(index + base);
        atomicAdd(&g_cnt[v.x], 1);
        atomicAdd(&g_cnt[v.y], 1);
        atomicAdd(&g_cnt[v.z], 1);
        atomicAdd(&g_cnt[v.w], 1);
    } else {
        for (long long e = base; e < E; e++)
            atomicAdd(&g_cnt[__ldg(&index[e])], 1);
    }
}

// ---------------------------------------------------------------------------
// K2: zero output + compute reciprocal counts
// ---------------------------------------------------------------------------
__global__ void prep_kernel(float4* __restrict__ out4, long long n4, int N) {
    long long i = (long long)blockIdx.x * blockDim.x + threadIdx.x;
    long long stride = (long long)gridDim.x * blockDim.x;
    for (long long k = i; k < n4; k += stride)
        out4[k] = make_float4(0.f, 0.f, 0.f, 0.f);
    for (long long k = i; k < N; k += stride) {
        int c = g_cnt[k];
        g_inv[k] = 1.0f / (float)max(c, 1);
    }
}

// ---------------------------------------------------------------------------
// K3: scatter-mean. 4 edges per warp; contributions pre-scaled by 1/count,
//     reduced with red.global.add.v4.f32. Output is the final mean.
// ---------------------------------------------------------------------------
__global__ __launch_bounds__(256) void scatter_kernel(
        const float4* __restrict__ msg4,
        const int* __restrict__ index,
        float* __restrict__ out,
        long long E) {
    long long warp_id = ((long long)blockIdx.x * blockDim.x + threadIdx.x) >> 5;
    int lane = threadIdx.x & 31;
    long long base = warp_id * 4;
    if (base >= E) return;
    int nb = (int)min(4LL, E - base);

    // lanes 0..3: coalesced index load + reciprocal lookup
    int seg = 0;
    float inv = 0.f;
    if (lane < nb) {
        seg = __ldg(&index[base + lane]);
        inv = g_inv[seg];
    }

    // front-batch the 4 independent row loads
    float4 v[4];
#pragma unroll
    for (int e = 0; e < 4; e++)
        if (e < nb) v[e] = __ldg(&msg4[(base + e) * (D / 4) + lane]);

#pragma unroll
    for (int e = 0; e < 4; e++) {
        if (e >= nb) break;
        int   segE = __shfl_sync(0xffffffffu, seg, e);
        float invE = __shfl_sync(0xffffffffu, inv, e);
        float4 w = v[e];
        w.x *= invE; w.y *= invE; w.z *= invE; w.w *= invE;
        float* dst = out + (long long)segE * D + lane * 4;
        asm volatile("red.global.add.v4.f32 [%0], {%1,%2,%3,%4};"
                     :: "l"(dst), "f"(w.x), "f"(w.y), "f"(w.z), "f"(w.w)
                     : "memory");
    }
}

// ---------------------------------------------------------------------------
extern "C" void kernel_launch(void* const* d_in, const int* in_sizes, int n_in,
                              void* d_out, int out_size) {
    const float4* msg4  = (const float4*)d_in[0];
    const int*    index = (const int*)d_in[1];
    // d_in[2] (t) unused by the reference
    float* out = (float*)d_out;

    long long E = in_sizes[1];
    int N = out_size / D;
    long long n4 = (long long)out_size / 4;

    zero_cnt_kernel<<<(N + 255) / 256, 256>>>(N);
    hist_kernel<<<(int)((E + 1023) / 1024), 256>>>(index, E);
    prep_kernel<<<2048, 256>>>((float4*)out, n4, N);
    {
        long long warps = (E + 3) / 4;
        long long threads = warps * 32;
        int blocks = (int)((threads + 255) / 256);
        scatter_kernel<<<blocks, 256>>>(msg4, index, out, E);
    }
}

// round 10
// speedup vs baseline: 1.8002x; 1.1580x over previous
#include <cuda_runtime.h>
#include <stdint.h>

#define D 128
#define MAX_N (1 << 18)

__device__ int   g_cnt[MAX_N];
__device__ float g_inv[MAX_N];

// ---------------------------------------------------------------------------
// K0: zero counts
// ---------------------------------------------------------------------------
__global__ void zero_cnt_kernel(int N) {
    int i = blockIdx.x * blockDim.x + threadIdx.x;
    if (i < N) g_cnt[i] = 0;
}

// ---------------------------------------------------------------------------
// K1: histogram of segment ids, 4 edges/thread (vectorized, streaming loads)
// ---------------------------------------------------------------------------
__global__ void hist_kernel(const int* __restrict__ index, long long E) {
    long long base = ((long long)blockIdx.x * blockDim.x + threadIdx.x) * 4;
    if (base >= E) return;
    if (base + 4 <= E) {
        int4 v = __ldcs((const int4*)(index + base));
        atomicAdd(&g_cnt[v.x], 1);
        atomicAdd(&g_cnt[v.y], 1);
        atomicAdd(&g_cnt[v.z], 1);
        atomicAdd(&g_cnt[v.w], 1);
    } else {
        for (long long e = base; e < E; e++)
            atomicAdd(&g_cnt[__ldg(&index[e])], 1);
    }
}

// ---------------------------------------------------------------------------
// K2: zero output + compute reciprocal counts
// ---------------------------------------------------------------------------
__global__ void prep_kernel(float4* __restrict__ out4, long long n4, int N) {
    long long i = (long long)blockIdx.x * blockDim.x + threadIdx.x;
    long long stride = (long long)gridDim.x * blockDim.x;
    for (long long k = i; k < n4; k += stride)
        out4[k] = make_float4(0.f, 0.f, 0.f, 0.f);
    for (long long k = i; k < N; k += stride) {
        int c = g_cnt[k];
        g_inv[k] = 1.0f / (float)max(c, 1);
    }
}

// ---------------------------------------------------------------------------
// K3: scatter-mean. 4 edges per warp; msg read with STREAMING (evict-first)
//     loads so the 1 GB one-touch stream does not thrash the hot 51 MB
//     output working set out of L2. Contributions pre-scaled by 1/count.
// ---------------------------------------------------------------------------
__global__ __launch_bounds__(256) void scatter_kernel(
        const float4* __restrict__ msg4,
        const int* __restrict__ index,
        float* __restrict__ out,
        long long E) {
    long long warp_id = ((long long)blockIdx.x * blockDim.x + threadIdx.x) >> 5;
    int lane = threadIdx.x & 31;
    long long base = warp_id * 4;
    if (base >= E) return;
    int nb = (int)min(4LL, E - base);

    // lanes 0..3: coalesced index load + reciprocal lookup
    int seg = 0;
    float inv = 0.f;
    if (lane < nb) {
        seg = __ldcs(&index[base + lane]);
        inv = g_inv[seg];
    }

    // front-batch the 4 independent row loads — streaming, evict-first
    float4 v[4];
#pragma unroll
    for (int e = 0; e < 4; e++)
        if (e < nb) v[e] = __ldcs(&msg4[(base + e) * (D / 4) + lane]);

#pragma unroll
    for (int e = 0; e < 4; e++) {
        if (e >= nb) break;
        int   segE = __shfl_sync(0xffffffffu, seg, e);
        float invE = __shfl_sync(0xffffffffu, inv, e);
        float4 w = v[e];
        w.x *= invE; w.y *= invE; w.z *= invE; w.w *= invE;
        float* dst = out + (long long)segE * D + lane * 4;
        asm volatile("red.global.add.v4.f32 [%0], {%1,%2,%3,%4};"
                     :: "l"(dst), "f"(w.x), "f"(w.y), "f"(w.z), "f"(w.w)
                     : "memory");
    }
}

// ---------------------------------------------------------------------------
extern "C" void kernel_launch(void* const* d_in, const int* in_sizes, int n_in,
                              void* d_out, int out_size) {
    const float4* msg4  = (const float4*)d_in[0];
    const int*    index = (const int*)d_in[1];
    // d_in[2] (t) unused by the reference
    float* out = (float*)d_out;

    long long E = in_sizes[1];
    int N = out_size / D;
    long long n4 = (long long)out_size / 4;

    zero_cnt_kernel<<<(N + 255) / 256, 256>>>(N);
    hist_kernel<<<(int)((E + 1023) / 1024), 256>>>(index, E);
    prep_kernel<<<2048, 256>>>((float4*)out, n4, N);
    {
        long long warps = (E + 3) / 4;
        long long threads = warps * 32;
        int blocks = (int)((threads + 255) / 256);
        scatter_kernel<<<blocks, 256>>>(msg4, index, out, E);
    }
}